// round 5
// baseline (speedup 1.0000x reference)
#include <cuda_runtime.h>

// Problem constants
#define BB   4096
#define TT   50
#define OBS  64
#define ACTD 16
#define DIN  80      // OBS + ACT
#define HH   256
#define G4   1024    // 4*H
#define NL   5
#define OUTD 64

// Kernel config: 512 small CTAs, 4 resident per SM
#define RPB  8             // batch rows per CTA
#define NCTA (BB / RPB)    // 512
#define NTH  128
#define AROWS 336          // 80 x-rows + 256 h-rows
#define RS   16            // duplicated row stride: 8 rows x 2 copies

// Shared memory (floats): two A buffers (duplicated layout) + bias cache
#define SZ_BUF (AROWS * RS)        // 5376
#define OFF_A0 0
#define OFF_A1 (SZ_BUF)
#define OFF_SB (2 * SZ_BUF)        // 10752
#define SMEM_FLOATS (OFF_SB + G4)  // 11776 floats = 47104 B/CTA (x4 = 188 KB)

typedef unsigned long long ull;

__device__ __forceinline__ float sigf(float x) {
    return __fdividef(1.0f, 1.0f + __expf(-x));
}

// packed f32x2 (sm_103a FFMA2 — PTX-only path)
__device__ __forceinline__ void ffma2(ull &d, ull a, ull b) {
    asm("fma.rn.f32x2 %0, %1, %2, %0;" : "+l"(d) : "l"(a), "l"(b));
}
__device__ __forceinline__ ull pk2(float lo, float hi) {
    ull r; asm("mov.b64 %0, {%1, %2};" : "=l"(r) : "f"(lo), "f"(hi)); return r;
}
__device__ __forceinline__ void upk2(ull v, float &lo, float &hi) {
    asm("mov.b64 {%0, %1}, %2;" : "=f"(lo), "=f"(hi) : "l"(v));
}

// Gate math; returns h_new, updates c in-place.
__device__ __forceinline__ float gatef(float zi, float zf, float zg, float zo,
                                       float &c)
{
    const float ig = sigf(zi);
    const float fg = sigf(zf);
    const float gg = zg * sigf(zg);       // silu
    const float og = sigf(zo);
    const float cn = fg * c + ig * gg;
    c = cn;
    return og * cn * sigf(cn);            // o * silu(c_new)
}

// Load x(t) into buffer (duplicated layout), rows are this CTA's 8 batch rows.
__device__ __forceinline__ void load_x(
    float* __restrict__ buf, const float* __restrict__ traj,
    const float* __restrict__ act, int row0, int t, int tid)
{
    #pragma unroll
    for (int it = 0; it < 5; ++it) {         // DIN*8 = 640 / 128
        const int i = tid + it * NTH;
        const int k = i >> 3, r = i & 7;
        const int row = row0 + r;
        float v;
        if (k < OBS) v = traj[((size_t)row * TT + t) * OBS + k];
        else         v = act [((size_t)row * TT + t) * ACTD + (k - OBS)];
        *(ull*)(buf + k * RS + (r << 1)) = pk2(v, v);
    }
}

__global__ void __launch_bounds__(NTH, 4)
lstm_fwd_kernel(const float* __restrict__ traj, const float* __restrict__ act,
                const float* __restrict__ Wi,   const float* __restrict__ Wh,
                const float* __restrict__ bh,   const float* __restrict__ mlpW,
                const float* __restrict__ mlpB, const float* __restrict__ Wout,
                const float* __restrict__ bout, float* __restrict__ out)
{
    extern __shared__ float sm[];
    float* sB = sm + OFF_SB;

    const int tid  = threadIdx.x;
    const int row0 = blockIdx.x * RPB;
    const int rgrp = tid & 1;        // 2 row groups x 4 rows
    const int cgrp = tid >> 1;       // 0..63 column pairs
    const int r0   = rgrp << 2;      // 0 or 4

    float* cA = sm + OFF_A0;         // current buffer
    float* nA = sm + OFF_A1;         // next buffer

    // cell state: creg[half*8 + c*4 + r]
    float creg[16];
    #pragma unroll
    for (int i = 0; i < 16; ++i) creg[i] = 0.0f;

    // init: zero h region of buf0, cache bh, load x(0)
    for (int i = tid; i < HH * RS; i += NTH) cA[DIN * RS + i] = 0.0f;
    for (int i = tid; i < G4; i += NTH) sB[i] = bh[i];
    load_x(cA, traj, act, row0, 0, tid);
    __syncthreads();

    // ============================ LSTM over time ============================
    for (int t = 0; t < TT; ++t) {
        #pragma unroll
        for (int half = 0; half < 2; ++half) {
            const int hk0 = (half << 7) + (cgrp << 1);
            const float* wI = Wi + hk0;     // + k*1024 + g*256
            const float* wH = Wh + hk0;

            // acc[g*4 + r], packed col pair (hk0, hk0+1); init with bias
            ull acc[16];
            {
                const ull b0 = pk2(sB[hk0],       sB[hk0 + 1]);
                const ull b1 = pk2(sB[256 + hk0], sB[256 + hk0 + 1]);
                const ull b2 = pk2(sB[512 + hk0], sB[512 + hk0 + 1]);
                const ull b3 = pk2(sB[768 + hk0], sB[768 + hk0 + 1]);
                #pragma unroll
                for (int r = 0; r < 4; ++r) {
                    acc[0 + r] = b0; acc[4 + r] = b1;
                    acc[8 + r] = b2; acc[12 + r] = b3;
                }
            }

            // x part: k = 0..79
            #pragma unroll 4
            for (int k = 0; k < DIN; ++k) {
                const ulonglong2 A0 = *(const ulonglong2*)(cA + k * RS + (r0 << 1));
                const ulonglong2 A1 = *(const ulonglong2*)(cA + k * RS + (r0 << 1) + 4);
                const float* wr = wI + (size_t)k * G4;
                #pragma unroll
                for (int g = 0; g < 4; ++g) {
                    const ull w = *(const ull*)(wr + (g << 8));
                    ffma2(acc[g * 4 + 0], w, A0.x);
                    ffma2(acc[g * 4 + 1], w, A0.y);
                    ffma2(acc[g * 4 + 2], w, A1.x);
                    ffma2(acc[g * 4 + 3], w, A1.y);
                }
            }
            // h part: k = 0..255 (rows DIN..335)
            #pragma unroll 4
            for (int k = 0; k < HH; ++k) {
                const ulonglong2 A0 = *(const ulonglong2*)(cA + (DIN + k) * RS + (r0 << 1));
                const ulonglong2 A1 = *(const ulonglong2*)(cA + (DIN + k) * RS + (r0 << 1) + 4);
                const float* wr = wH + (size_t)k * G4;
                #pragma unroll
                for (int g = 0; g < 4; ++g) {
                    const ull w = *(const ull*)(wr + (g << 8));
                    ffma2(acc[g * 4 + 0], w, A0.x);
                    ffma2(acc[g * 4 + 1], w, A0.y);
                    ffma2(acc[g * 4 + 2], w, A1.x);
                    ffma2(acc[g * 4 + 3], w, A1.y);
                }
            }

            // gate epilogue -> write h_new directly into NEXT buffer (packed dup)
            #pragma unroll
            for (int r = 0; r < 4; ++r) {
                float zi0, zi1, zf0, zf1, zg0, zg1, zo0, zo1;
                upk2(acc[0  + r], zi0, zi1);
                upk2(acc[4  + r], zf0, zf1);
                upk2(acc[8  + r], zg0, zg1);
                upk2(acc[12 + r], zo0, zo1);
                const float h0 = gatef(zi0, zf0, zg0, zo0, creg[half * 8 + 0 + r]);
                const float h1 = gatef(zi1, zf1, zg1, zo1, creg[half * 8 + 4 + r]);
                const int row = r0 + r;
                *(ull*)(nA + (DIN + hk0)     * RS + (row << 1)) = pk2(h0, h0);
                *(ull*)(nA + (DIN + hk0 + 1) * RS + (row << 1)) = pk2(h1, h1);
            }
        }

        // preload x(t+1) into next buffer, then single barrier + swap
        if (t + 1 < TT) load_x(nA, traj, act, row0, t + 1, tid);
        __syncthreads();
        float* tmp = cA; cA = nA; nA = tmp;
    }

    // ============================ MLP head ============================
    // Thread: 4 rows x 4 cols (c0 = cgrp*4). Per kk: 2 LDS.128 + 1 LDG.128.
    for (int l = 0; l < NL; ++l) {
        const float* Wl = mlpW + (size_t)l * HH * HH + (cgrp << 2);
        const int c0 = cgrp << 2;

        ull acc[8];                         // [cp(2)][r(4)]
        {
            const ull b01 = pk2(mlpB[l * HH + c0],     mlpB[l * HH + c0 + 1]);
            const ull b23 = pk2(mlpB[l * HH + c0 + 2], mlpB[l * HH + c0 + 3]);
            #pragma unroll
            for (int r = 0; r < 4; ++r) { acc[r] = b01; acc[4 + r] = b23; }
        }

        #pragma unroll 4
        for (int k = 0; k < HH; ++k) {
            const ulonglong2 A0 = *(const ulonglong2*)(cA + (DIN + k) * RS + (r0 << 1));
            const ulonglong2 A1 = *(const ulonglong2*)(cA + (DIN + k) * RS + (r0 << 1) + 4);
            const ulonglong2 w = *(const ulonglong2*)(Wl + (size_t)k * HH);
            ffma2(acc[0], w.x, A0.x);  ffma2(acc[1], w.x, A0.y);
            ffma2(acc[2], w.x, A1.x);  ffma2(acc[3], w.x, A1.y);
            ffma2(acc[4], w.y, A0.x);  ffma2(acc[5], w.y, A0.y);
            ffma2(acc[6], w.y, A1.x);  ffma2(acc[7], w.y, A1.y);
        }

        // silu epilogue -> next buffer (duplicated)
        #pragma unroll
        for (int cp = 0; cp < 2; ++cp) {
            #pragma unroll
            for (int r = 0; r < 4; ++r) {
                float v0, v1;
                upk2(acc[cp * 4 + r], v0, v1);
                v0 = v0 * sigf(v0);
                v1 = v1 * sigf(v1);
                const int row = r0 + r;
                *(ull*)(nA + (DIN + c0 + cp * 2)     * RS + (row << 1)) = pk2(v0, v0);
                *(ull*)(nA + (DIN + c0 + cp * 2 + 1) * RS + (row << 1)) = pk2(v1, v1);
            }
        }
        __syncthreads();
        float* tmp = cA; cA = nA; nA = tmp;
    }

    // ---- output layer: [8x256] @ [256x64] + bout
    // Thread: 4 rows x 2 cols, K split in half across cgrp>>5; reduce via nA.
    {
        const int khalf = cgrp >> 5;        // 0 or 1
        const int c0    = (cgrp & 31) << 1;
        const float* Wo = Wout + c0;
        const int kb    = khalf << 7;

        ull acco[4];
        const ull binit = khalf ? 0ull : pk2(bout[c0], bout[c0 + 1]);
        #pragma unroll
        for (int i = 0; i < 4; ++i) acco[i] = binit;

        #pragma unroll 4
        for (int k = 0; k < 128; ++k) {
            const ulonglong2 A0 = *(const ulonglong2*)(cA + (DIN + kb + k) * RS + (r0 << 1));
            const ulonglong2 A1 = *(const ulonglong2*)(cA + (DIN + kb + k) * RS + (r0 << 1) + 4);
            const ull w = *(const ull*)(Wo + (size_t)(kb + k) * OUTD);
            ffma2(acco[0], w, A0.x);
            ffma2(acco[1], w, A0.y);
            ffma2(acco[2], w, A1.x);
            ffma2(acco[3], w, A1.y);
        }
        // khalf=1 parks partials in scratch (nA area), khalf=0 adds + stores
        float* scr = nA;                     // 64 cols x 8 rows
        if (khalf == 1) {
            #pragma unroll
            for (int r = 0; r < 4; ++r) {
                float v0, v1; upk2(acco[r], v0, v1);
                scr[(c0 + 0) * 8 + r0 + r] = v0;
                scr[(c0 + 1) * 8 + r0 + r] = v1;
            }
        }
        __syncthreads();
        if (khalf == 0) {
            #pragma unroll
            for (int r = 0; r < 4; ++r) {
                float v0, v1; upk2(acco[r], v0, v1);
                v0 += scr[(c0 + 0) * 8 + r0 + r];
                v1 += scr[(c0 + 1) * 8 + r0 + r];
                *(float2*)(out + (size_t)(row0 + r0 + r) * OUTD + c0) =
                    make_float2(v0, v1);
            }
        }
    }
}

extern "C" void kernel_launch(void* const* d_in, const int* in_sizes, int n_in,
                              void* d_out, int out_size)
{
    const float* traj = (const float*)d_in[0];
    const float* act  = (const float*)d_in[1];
    const float* Wi   = (const float*)d_in[2];
    const float* Wh   = (const float*)d_in[3];
    const float* bh   = (const float*)d_in[4];
    const float* mlpW = (const float*)d_in[5];
    const float* mlpB = (const float*)d_in[6];
    const float* Wout = (const float*)d_in[7];
    const float* bout = (const float*)d_in[8];
    float* out = (float*)d_out;

    cudaFuncSetAttribute(lstm_fwd_kernel,
                         cudaFuncAttributeMaxDynamicSharedMemorySize,
                         SMEM_FLOATS * (int)sizeof(float));
    lstm_fwd_kernel<<<NCTA, NTH, SMEM_FLOATS * sizeof(float)>>>(
        traj, act, Wi, Wh, bh, mlpW, mlpB, Wout, bout, out);
}

// round 6
// speedup vs baseline: 1.1633x; 1.1633x over previous
#include <cuda_runtime.h>

// Problem constants
#define BB   4096
#define TT   50
#define OBS  64
#define ACTD 16
#define DIN  80      // OBS + ACT
#define HH   256
#define G4   1024    // 4*H
#define NL   5
#define OUTD 64
#define KTOT 336     // DIN + HH

// Kernel config (R3 skeleton)
#define RPB  32            // batch rows per CTA
#define NCTA (BB / RPB)    // 128
#define NTH  512
#define SAS  36            // sA row stride in floats

// Shared memory (floats): double-buffered A + bias cache
#define SZ_BUF (KTOT * SAS)        // 12096
#define OFF_A0 0
#define OFF_A1 (SZ_BUF)
#define OFF_SB (2 * SZ_BUF)        // 24192
#define SMEM_FLOATS (OFF_SB + G4)  // 25216 floats = 100864 B

typedef unsigned long long ull;

// Repacked LSTM weights: W2[k][cp][g][c], k<336, cp<128, g<4, c<2
// (8 contiguous floats per (k,cp) -> two LDG.128 per k per thread)
__device__ float W2buf[KTOT * G4];

__device__ __forceinline__ float sigf(float x) {
    return __fdividef(1.0f, 1.0f + __expf(-x));
}

// packed f32x2 (sm_103a FFMA2 — PTX-only path)
__device__ __forceinline__ void ffma2(ull &d, ull a, ull b) {
    asm("fma.rn.f32x2 %0, %1, %2, %0;" : "+l"(d) : "l"(a), "l"(b));
}
__device__ __forceinline__ ull pk2(float lo, float hi) {
    ull r; asm("mov.b64 %0, {%1, %2};" : "=l"(r) : "f"(lo), "f"(hi)); return r;
}
__device__ __forceinline__ void upk2(ull v, float &lo, float &hi) {
    asm("mov.b64 {%0, %1}, %2;" : "=f"(lo), "=f"(hi) : "l"(v));
}

__device__ __forceinline__ float gatef(float zi, float zf, float zg, float zo,
                                       float &c)
{
    const float ig = sigf(zi);
    const float fg = sigf(zf);
    const float gg = zg * sigf(zg);       // silu
    const float og = sigf(zo);
    const float cn = fg * c + ig * gg;
    c = cn;
    return og * cn * sigf(cn);            // o * silu(c_new)
}

// ---------------- prepass: repack [Wi;Wh] into gate-interleaved W2 ----------
__global__ void repack_kernel(const float* __restrict__ Wi,
                              const float* __restrict__ Wh)
{
    const int i = blockIdx.x * blockDim.x + threadIdx.x;
    if (i >= KTOT * G4) return;
    const int k   = i >> 10;
    const int rem = i & 1023;
    const int cp  = rem >> 3;
    const int g   = (rem >> 1) & 3;
    const int c   = rem & 1;
    const int col = (g << 8) + (cp << 1) + c;
    W2buf[i] = (k < DIN) ? Wi[(size_t)k * G4 + col]
                         : Wh[(size_t)(k - DIN) * G4 + col];
}

// ---------------- main kernel ----------------
__global__ void __launch_bounds__(NTH, 1)
lstm_fwd_kernel(const float* __restrict__ traj, const float* __restrict__ act,
                const float* __restrict__ bh,   const float* __restrict__ mlpW,
                const float* __restrict__ mlpB, const float* __restrict__ Wout,
                const float* __restrict__ bout, float* __restrict__ out)
{
    extern __shared__ float sm[];
    float* sB = sm + OFF_SB;

    const int tid  = threadIdx.x;
    const int row0 = blockIdx.x * RPB;
    const int rgrp = tid & 7;        // 8 row groups x 4 rows
    const int cgrp = tid >> 3;       // 0..63 column pairs per half
    const int r0   = rgrp << 2;

    float* cA = sm + OFF_A0;         // current A buffer [336][36]
    float* nA = sm + OFF_A1;         // next A buffer

    // cell state: creg[half*8 + c*4 + r]
    float creg[16];
    #pragma unroll
    for (int i = 0; i < 16; ++i) creg[i] = 0.0f;

    // init: zero h region of buf0, cache bh, load x(0)
    for (int i = tid; i < HH * SAS; i += NTH) cA[DIN * SAS + i] = 0.0f;
    for (int i = tid; i < G4; i += NTH) sB[i] = bh[i];
    for (int i = tid; i < DIN * RPB; i += NTH) {
        const int r = i & 31, k = i >> 5;
        const int row = row0 + r;
        float v;
        if (k < OBS) v = traj[((size_t)row * TT) * OBS + k];
        else         v = act [((size_t)row * TT) * ACTD + (k - OBS)];
        cA[k * SAS + r] = v;
    }
    __syncthreads();

    // ============================ LSTM over time ============================
    for (int t = 0; t < TT; ++t) {
        #pragma unroll
        for (int half = 0; half < 2; ++half) {
            const int cp  = (half << 6) + cgrp;     // 0..127
            const int hk0 = cp << 1;                // 0..254
            const float* wp = W2buf + (cp << 3);

            ull acc[16];                            // [g][r]
            #pragma unroll
            for (int i = 0; i < 16; ++i) acc[i] = 0ull;

            // unified K loop over x (0..79) and h (80..335)
            #pragma unroll 4
            for (int k = 0; k < KTOT; ++k) {
                const float4 a = *(const float4*)(cA + k * SAS + r0);
                const ull a0 = pk2(a.x, a.x), a1 = pk2(a.y, a.y);
                const ull a2 = pk2(a.z, a.z), a3 = pk2(a.w, a.w);
                const ulonglong2 wa = *(const ulonglong2*)(wp + (size_t)k * G4);
                const ulonglong2 wb = *(const ulonglong2*)(wp + (size_t)k * G4 + 4);
                ffma2(acc[ 0], wa.x, a0); ffma2(acc[ 1], wa.x, a1);
                ffma2(acc[ 2], wa.x, a2); ffma2(acc[ 3], wa.x, a3);
                ffma2(acc[ 4], wa.y, a0); ffma2(acc[ 5], wa.y, a1);
                ffma2(acc[ 6], wa.y, a2); ffma2(acc[ 7], wa.y, a3);
                ffma2(acc[ 8], wb.x, a0); ffma2(acc[ 9], wb.x, a1);
                ffma2(acc[10], wb.x, a2); ffma2(acc[11], wb.x, a3);
                ffma2(acc[12], wb.y, a0); ffma2(acc[13], wb.y, a1);
                ffma2(acc[14], wb.y, a2); ffma2(acc[15], wb.y, a3);
            }

            // gate epilogue -> h_new straight into NEXT buffer
            const float bi0 = sB[hk0],       bi1 = sB[hk0 + 1];
            const float bf0 = sB[256 + hk0], bf1 = sB[256 + hk0 + 1];
            const float bg0 = sB[512 + hk0], bg1 = sB[512 + hk0 + 1];
            const float bo0 = sB[768 + hk0], bo1 = sB[768 + hk0 + 1];
            #pragma unroll
            for (int r = 0; r < 4; ++r) {
                float zi0, zi1, zf0, zf1, zg0, zg1, zo0, zo1;
                upk2(acc[ 0 + r], zi0, zi1);
                upk2(acc[ 4 + r], zf0, zf1);
                upk2(acc[ 8 + r], zg0, zg1);
                upk2(acc[12 + r], zo0, zo1);
                const float h0 = gatef(zi0 + bi0, zf0 + bf0, zg0 + bg0, zo0 + bo0,
                                       creg[half * 8 + 0 + r]);
                const float h1 = gatef(zi1 + bi1, zf1 + bf1, zg1 + bg1, zo1 + bo1,
                                       creg[half * 8 + 4 + r]);
                const int row = r0 + r;
                nA[(DIN + hk0)     * SAS + row] = h0;
                nA[(DIN + hk0 + 1) * SAS + row] = h1;
            }
        }

        // preload x(t+1) into next buffer; single barrier; swap
        if (t + 1 < TT) {
            for (int i = tid; i < DIN * RPB; i += NTH) {
                const int r = i & 31, k = i >> 5;
                const int row = row0 + r;
                float v;
                if (k < OBS) v = traj[((size_t)row * TT + t + 1) * OBS + k];
                else         v = act [((size_t)row * TT + t + 1) * ACTD + (k - OBS)];
                nA[k * SAS + r] = v;
            }
        }
        __syncthreads();
        float* tmp = cA; cA = nA; nA = tmp;
    }

    // ============================ MLP head ============================
    // Thread: 4 rows x 4 cols (c0 = cgrp*4). Per kk: 1 LDS.128 + 1 LDG.128.
    for (int l = 0; l < NL; ++l) {
        const float* Wl = mlpW + (size_t)l * HH * HH + (cgrp << 2);
        const int c0 = cgrp << 2;

        ull acc[8];                        // [cp(2)][r(4)]
        #pragma unroll
        for (int i = 0; i < 8; ++i) acc[i] = 0ull;

        #pragma unroll 4
        for (int k = 0; k < HH; ++k) {
            const float4 a = *(const float4*)(cA + (DIN + k) * SAS + r0);
            const ull a0 = pk2(a.x, a.x), a1 = pk2(a.y, a.y);
            const ull a2 = pk2(a.z, a.z), a3 = pk2(a.w, a.w);
            const ulonglong2 w = *(const ulonglong2*)(Wl + (size_t)k * HH);
            ffma2(acc[0], w.x, a0);  ffma2(acc[1], w.x, a1);
            ffma2(acc[2], w.x, a2);  ffma2(acc[3], w.x, a3);
            ffma2(acc[4], w.y, a0);  ffma2(acc[5], w.y, a1);
            ffma2(acc[6], w.y, a2);  ffma2(acc[7], w.y, a3);
        }

        // silu epilogue -> next buffer
        const float b0 = mlpB[l * HH + c0],     b1 = mlpB[l * HH + c0 + 1];
        const float b2 = mlpB[l * HH + c0 + 2], b3 = mlpB[l * HH + c0 + 3];
        #pragma unroll
        for (int r = 0; r < 4; ++r) {
            float v0, v1, v2, v3;
            upk2(acc[0 + r], v0, v1);
            upk2(acc[4 + r], v2, v3);
            v0 += b0; v1 += b1; v2 += b2; v3 += b3;
            const int row = r0 + r;
            nA[(DIN + c0 + 0) * SAS + row] = v0 * sigf(v0);
            nA[(DIN + c0 + 1) * SAS + row] = v1 * sigf(v1);
            nA[(DIN + c0 + 2) * SAS + row] = v2 * sigf(v2);
            nA[(DIN + c0 + 3) * SAS + row] = v3 * sigf(v3);
        }
        __syncthreads();
        float* tmp = cA; cA = nA; nA = tmp;
    }

    // ---- output layer: [32x256] @ [256x64] + bout; K split across cgrp>>5
    {
        const int khalf = cgrp >> 5;        // 0 or 1
        const int c0    = (cgrp & 31) << 1;
        const float* Wo = Wout + c0;
        const int kb    = khalf << 7;

        ull acco[4];
        #pragma unroll
        for (int i = 0; i < 4; ++i) acco[i] = 0ull;

        #pragma unroll 4
        for (int k = 0; k < 128; ++k) {
            const float4 a = *(const float4*)(cA + (DIN + kb + k) * SAS + r0);
            const ull w = *(const ull*)(Wo + (size_t)(kb + k) * OUTD);
            ffma2(acco[0], w, pk2(a.x, a.x));
            ffma2(acco[1], w, pk2(a.y, a.y));
            ffma2(acco[2], w, pk2(a.z, a.z));
            ffma2(acco[3], w, pk2(a.w, a.w));
        }
        float* scr = nA;                    // scratch: [64 cols][36] rows 0..31
        if (khalf == 1) {
            #pragma unroll
            for (int r = 0; r < 4; ++r) {
                float v0, v1; upk2(acco[r], v0, v1);
                scr[(c0 + 0) * SAS + r0 + r] = v0;
                scr[(c0 + 1) * SAS + r0 + r] = v1;
            }
        }
        __syncthreads();
        if (khalf == 0) {
            const float b0 = bout[c0], b1 = bout[c0 + 1];
            #pragma unroll
            for (int r = 0; r < 4; ++r) {
                float v0, v1; upk2(acco[r], v0, v1);
                v0 += scr[(c0 + 0) * SAS + r0 + r] + b0;
                v1 += scr[(c0 + 1) * SAS + r0 + r] + b1;
                *(float2*)(out + (size_t)(row0 + r0 + r) * OUTD + c0) =
                    make_float2(v0, v1);
            }
        }
    }
}

extern "C" void kernel_launch(void* const* d_in, const int* in_sizes, int n_in,
                              void* d_out, int out_size)
{
    const float* traj = (const float*)d_in[0];
    const float* act  = (const float*)d_in[1];
    const float* Wi   = (const float*)d_in[2];
    const float* Wh   = (const float*)d_in[3];
    const float* bh   = (const float*)d_in[4];
    const float* mlpW = (const float*)d_in[5];
    const float* mlpB = (const float*)d_in[6];
    const float* Wout = (const float*)d_in[7];
    const float* bout = (const float*)d_in[8];
    float* out = (float*)d_out;

    repack_kernel<<<(KTOT * G4 + 511) / 512, 512>>>(Wi, Wh);

    cudaFuncSetAttribute(lstm_fwd_kernel,
                         cudaFuncAttributeMaxDynamicSharedMemorySize,
                         SMEM_FLOATS * (int)sizeof(float));
    lstm_fwd_kernel<<<NCTA, NTH, SMEM_FLOATS * sizeof(float)>>>(
        traj, act, bh, mlpW, mlpB, Wout, bout, out);
}